// round 3
// baseline (speedup 1.0000x reference)
#include <cuda_runtime.h>
#include <math.h>

// ---------------- problem dims (fixed) ----------------
#define Bb   4
#define Tt   1024
#define Dd   1024
#define Hh   16
#define HSs  64
#define DFF  4096
#define ROWS (Bb*Tt)      // 4096

// ---------------- scratch (device globals; no allocs allowed) ----------------
__device__ float g_hn [ROWS*Dd];
__device__ float g_q  [ROWS*2048];
__device__ float g_k  [ROWS*2048];
__device__ float g_v  [ROWS*1024];
__device__ float g_ao [ROWS*1024];
__device__ float g_h1 [ROWS*Dd];
__device__ float g_h2 [ROWS*Dd];
__device__ float g_hn2[ROWS*Dd];
__device__ float g_m1 [ROWS*DFF];
__device__ float g_m2 [ROWS*DFF];
__device__ float g_lam[32];

// ---------------- helpers ----------------
__device__ __forceinline__ float red_max16(float v) {
#pragma unroll
    for (int o = 8; o; o >>= 1) v = fmaxf(v, __shfl_xor_sync(0xffffffffu, v, o));
    return v;
}
__device__ __forceinline__ float red_sum16(float v) {
#pragma unroll
    for (int o = 8; o; o >>= 1) v += __shfl_xor_sync(0xffffffffu, v, o);
    return v;
}

// ---------------- rmsnorm: one block per row of 1024 ----------------
__global__ __launch_bounds__(256) void rmsnorm_kernel(
    const float* __restrict__ x, const float* __restrict__ g, float* __restrict__ out)
{
    __shared__ float red[8];
    __shared__ float sscale;
    const int row = blockIdx.x;
    const int t = threadIdx.x;
    const float4* xr = (const float4*)(x + (size_t)row * 1024);
    float4 v = xr[t];
    float ss = v.x*v.x + v.y*v.y + v.z*v.z + v.w*v.w;
#pragma unroll
    for (int o = 16; o; o >>= 1) ss += __shfl_xor_sync(0xffffffffu, ss, o);
    if ((t & 31) == 0) red[t >> 5] = ss;
    __syncthreads();
    if (t == 0) {
        float s = 0.f;
#pragma unroll
        for (int i = 0; i < 8; ++i) s += red[i];
        sscale = rsqrtf(s * (1.0f/1024.0f) + 1e-6f);
    }
    __syncthreads();
    const float sc = sscale;
    float4 gv = ((const float4*)g)[t];
    float4 o;
    o.x = v.x*sc*gv.x; o.y = v.y*sc*gv.y; o.z = v.z*sc*gv.z; o.w = v.w*sc*gv.w;
    ((float4*)(out + (size_t)row * 1024))[t] = o;
}

// ---------------- lambda: lam[h] = exp(sum lq1*lk1) - exp(sum lq2*lk2) + 0.8 ----------------
__global__ void lambda_kernel(const float* __restrict__ lq1, const float* __restrict__ lk1,
                              const float* __restrict__ lq2, const float* __restrict__ lk2,
                              float* __restrict__ lam)
{
    const int h = blockIdx.x;
    const int lane = threadIdx.x;   // 32 threads
    float s1 = 0.f, s2 = 0.f;
    for (int d = lane; d < 64; d += 32) {
        s1 += lq1[h*64 + d] * lk1[h*64 + d];
        s2 += lq2[h*64 + d] * lk2[h*64 + d];
    }
#pragma unroll
    for (int o = 16; o; o >>= 1) {
        s1 += __shfl_xor_sync(0xffffffffu, s1, o);
        s2 += __shfl_xor_sync(0xffffffffu, s2, o);
    }
    if (lane == 0) lam[h] = expf(s1) - expf(s2) + 0.8f;
}

// ---------------- SGEMM: C[M,N] = A[M,K] @ B[K,N]; mode 0 plain, 1 +R, 2 *2 ----------------
__global__ __launch_bounds__(256) void sgemm_kernel(
    const float* __restrict__ A, const float* __restrict__ B,
    const float* __restrict__ R, float* __restrict__ C,
    int M, int N, int K, int mode)
{
    __shared__ float As[2][16][132];
    __shared__ float Bs[2][16][128];
    const int tid = threadIdx.x;
    const int tx = tid & 15, ty = tid >> 4;
    const int bm = blockIdx.y * 128, bn = blockIdx.x * 128;

    const int arow = tid >> 2;
    const int acol = (tid & 3) << 2;
    const int brow = tid >> 5;
    const int bcol = (tid & 31) << 2;

    const float* Ap = A + (size_t)(bm + arow) * K + acol;
    const float* Bp = B + (size_t)brow * N + bn + bcol;

    float4 a0 = *(const float4*)(Ap);
    float4 a1 = *(const float4*)(Ap + (size_t)64 * K);
    float4 b0 = *(const float4*)(Bp);
    float4 b1 = *(const float4*)(Bp + (size_t)8 * N);

    As[0][acol+0][arow] = a0.x; As[0][acol+1][arow] = a0.y;
    As[0][acol+2][arow] = a0.z; As[0][acol+3][arow] = a0.w;
    As[0][acol+0][arow+64] = a1.x; As[0][acol+1][arow+64] = a1.y;
    As[0][acol+2][arow+64] = a1.z; As[0][acol+3][arow+64] = a1.w;
    *(float4*)&Bs[0][brow][bcol]   = b0;
    *(float4*)&Bs[0][brow+8][bcol] = b1;
    __syncthreads();

    float acc[8][8];
#pragma unroll
    for (int i = 0; i < 8; ++i)
#pragma unroll
        for (int j = 0; j < 8; ++j) acc[i][j] = 0.f;

    const int nt = K >> 4;
    for (int t = 0; t < nt; ++t) {
        const int cur = t & 1;
        if (t + 1 < nt) {
            const float* Ap2 = Ap + (t + 1) * 16;
            const float* Bp2 = Bp + (size_t)(t + 1) * 16 * N;
            a0 = *(const float4*)(Ap2);
            a1 = *(const float4*)(Ap2 + (size_t)64 * K);
            b0 = *(const float4*)(Bp2);
            b1 = *(const float4*)(Bp2 + (size_t)8 * N);
        }
#pragma unroll
        for (int kk = 0; kk < 16; ++kk) {
            float ar[8], br[8];
            *(float4*)&ar[0] = *(const float4*)&As[cur][kk][ty*8];
            *(float4*)&ar[4] = *(const float4*)&As[cur][kk][ty*8+4];
            *(float4*)&br[0] = *(const float4*)&Bs[cur][kk][tx*8];
            *(float4*)&br[4] = *(const float4*)&Bs[cur][kk][tx*8+4];
#pragma unroll
            for (int i = 0; i < 8; ++i)
#pragma unroll
                for (int j = 0; j < 8; ++j)
                    acc[i][j] += ar[i] * br[j];
        }
        if (t + 1 < nt) {
            const int nxt = cur ^ 1;
            As[nxt][acol+0][arow] = a0.x; As[nxt][acol+1][arow] = a0.y;
            As[nxt][acol+2][arow] = a0.z; As[nxt][acol+3][arow] = a0.w;
            As[nxt][acol+0][arow+64] = a1.x; As[nxt][acol+1][arow+64] = a1.y;
            As[nxt][acol+2][arow+64] = a1.z; As[nxt][acol+3][arow+64] = a1.w;
            *(float4*)&Bs[nxt][brow][bcol]   = b0;
            *(float4*)&Bs[nxt][brow+8][bcol] = b1;
            __syncthreads();
        }
    }

#pragma unroll
    for (int i = 0; i < 8; ++i) {
        const int row = bm + ty*8 + i;
#pragma unroll
        for (int j = 0; j < 8; j += 4) {
            const int col = bn + tx*8 + j;
            float4 r;
            r.x = acc[i][j]; r.y = acc[i][j+1]; r.z = acc[i][j+2]; r.w = acc[i][j+3];
            if (mode == 2) { r.x *= 2.f; r.y *= 2.f; r.z *= 2.f; r.w *= 2.f; }
            else if (mode == 1) {
                float4 d = *(const float4*)&R[(size_t)row * N + col];
                r.x += d.x; r.y += d.y; r.z += d.z; r.w += d.w;
            }
            *(float4*)&C[(size_t)row * N + col] = r;
        }
    }
}

// ---------------- flash diff-attention ----------------
// Q: (B,T,H,2,64), K: (B,S,H,2,64), V: (B,S,H,64); out (B,T,H,64), combined
// with lam and per-row rmsnorm * 0.2 in epilogue.
#define FL_SMEM ((4*64*68 + 64*64) * 4)

__global__ __launch_bounds__(256) void flash_diff_kernel(
    const float* __restrict__ Q, const float* __restrict__ Kg,
    const float* __restrict__ Vg, const float* __restrict__ lamp,
    float* __restrict__ Og, int Sq, int Sk, int causal)
{
    extern __shared__ float sm[];
    float* Qs1 = sm;                  // 64x68
    float* Qs2 = Qs1 + 64*68;
    float* KP1 = Qs2 + 64*68;         // K1 tile, reused as P1
    float* KP2 = KP1 + 64*68;
    float* Vs  = KP2 + 64*68;         // 64x64

    const int tid = threadIdx.x;
    const int tx = tid & 15, ty = tid >> 4;
    const int qt = blockIdx.x, h = blockIdx.y, b = blockIdx.z;

    // load Q tiles (both components)
    {
        const int r = tid >> 2;
        const int d0 = (tid & 3) << 4;
        const float* qb = Q + ((size_t)(b*Sq + qt*64 + r) * Hh + h) * 128 + d0;
#pragma unroll
        for (int u = 0; u < 16; u += 4) {
            *(float4*)&Qs1[r*68 + d0 + u] = *(const float4*)(qb + u);
            *(float4*)&Qs2[r*68 + d0 + u] = *(const float4*)(qb + 64 + u);
        }
    }

    float O1[4][4], O2[4][4];
    float rm1[4], rl1[4], rm2[4], rl2[4];
#pragma unroll
    for (int i = 0; i < 4; ++i) {
        rm1[i] = rm2[i] = -1e30f; rl1[i] = rl2[i] = 0.f;
#pragma unroll
        for (int j = 0; j < 4; ++j) { O1[i][j] = 0.f; O2[i][j] = 0.f; }
    }
    const float scale = 0.125f;     // 1/sqrt(64)
    const int nkt = causal ? (qt + 1) : (Sk >> 6);

    for (int kt = 0; kt < nkt; ++kt) {
        __syncthreads();   // prev PV done reading KP/Vs (and Q stores visible, iter 0)
        {
            const int c = tid >> 2;
            const int d0 = (tid & 3) << 4;
            const float* kb = Kg + ((size_t)(b*Sk + kt*64 + c) * Hh + h) * 128 + d0;
            const float* vb = Vg + ((size_t)(b*Sk + kt*64 + c) * Hh + h) * 64 + d0;
#pragma unroll
            for (int u = 0; u < 16; u += 4) {
                *(float4*)&KP1[c*68 + d0 + u] = *(const float4*)(kb + u);
                *(float4*)&KP2[c*68 + d0 + u] = *(const float4*)(kb + 64 + u);
                *(float4*)&Vs [c*64 + d0 + u] = *(const float4*)(vb + u);
            }
        }
        __syncthreads();

        // ---- scores: S = Q K^T ----
        float s1[4][4], s2[4][4];
#pragma unroll
        for (int i = 0; i < 4; ++i)
#pragma unroll
            for (int j = 0; j < 4; ++j) { s1[i][j] = 0.f; s2[i][j] = 0.f; }

#pragma unroll 4
        for (int k4 = 0; k4 < 64; k4 += 4) {
            float4 qa[4], qb[4], ka[4], kb[4];
#pragma unroll
            for (int i = 0; i < 4; ++i) {
                qa[i] = *(const float4*)&Qs1[(ty*4+i)*68 + k4];
                qb[i] = *(const float4*)&Qs2[(ty*4+i)*68 + k4];
            }
#pragma unroll
            for (int j = 0; j < 4; ++j) {
                ka[j] = *(const float4*)&KP1[(j*16+tx)*68 + k4];
                kb[j] = *(const float4*)&KP2[(j*16+tx)*68 + k4];
            }
#pragma unroll
            for (int i = 0; i < 4; ++i)
#pragma unroll
                for (int j = 0; j < 4; ++j) {
                    s1[i][j] += qa[i].x*ka[j].x + qa[i].y*ka[j].y + qa[i].z*ka[j].z + qa[i].w*ka[j].w;
                    s2[i][j] += qb[i].x*kb[j].x + qb[i].y*kb[j].y + qb[i].z*kb[j].z + qb[i].w*kb[j].w;
                }
        }

        const bool maskdiag = (causal != 0) && (kt == qt);
        __syncthreads();   // everyone done reading KP -> safe to overwrite with P

        // ---- online softmax (both matrices); write P over KP ----
#pragma unroll
        for (int i = 0; i < 4; ++i) {
            const int r = ty*4 + i;
            // matrix 1
            float tm = -1e30f;
#pragma unroll
            for (int j = 0; j < 4; ++j) {
                s1[i][j] *= scale;
                if (maskdiag && (j*16 + tx) > r) s1[i][j] = -1e9f;
                tm = fmaxf(tm, s1[i][j]);
            }
            tm = red_max16(tm);
            float mn = fmaxf(rm1[i], tm);
            float al = __expf(rm1[i] - mn);
            rm1[i] = mn;
            float rs = 0.f;
#pragma unroll
            for (int j = 0; j < 4; ++j) {
                float p = __expf(s1[i][j] - mn);
                rs += p;
                KP1[r*68 + j*16 + tx] = p;
            }
            rs = red_sum16(rs);
            rl1[i] = rl1[i]*al + rs;
#pragma unroll
            for (int j = 0; j < 4; ++j) O1[i][j] *= al;
            // matrix 2
            float tm2 = -1e30f;
#pragma unroll
            for (int j = 0; j < 4; ++j) {
                s2[i][j] *= scale;
                if (maskdiag && (j*16 + tx) > r) s2[i][j] = -1e9f;
                tm2 = fmaxf(tm2, s2[i][j]);
            }
            tm2 = red_max16(tm2);
            float mn2 = fmaxf(rm2[i], tm2);
            float al2 = __expf(rm2[i] - mn2);
            rm2[i] = mn2;
            float rs2 = 0.f;
#pragma unroll
            for (int j = 0; j < 4; ++j) {
                float p = __expf(s2[i][j] - mn2);
                rs2 += p;
                KP2[r*68 + j*16 + tx] = p;
            }
            rs2 = red_sum16(rs2);
            rl2[i] = rl2[i]*al2 + rs2;
#pragma unroll
            for (int j = 0; j < 4; ++j) O2[i][j] *= al2;
        }
        __syncthreads();

        // ---- O += P V ----
#pragma unroll 4
        for (int c4 = 0; c4 < 64; c4 += 4) {
            float4 pa[4], pb[4];
#pragma unroll
            for (int i = 0; i < 4; ++i) {
                pa[i] = *(const float4*)&KP1[(ty*4+i)*68 + c4];
                pb[i] = *(const float4*)&KP2[(ty*4+i)*68 + c4];
            }
#pragma unroll
            for (int cc = 0; cc < 4; ++cc) {
                float vv[4];
#pragma unroll
                for (int j = 0; j < 4; ++j) vv[j] = Vs[(c4+cc)*64 + j*16 + tx];
#pragma unroll
                for (int i = 0; i < 4; ++i) {
                    const float p1v = ((const float*)&pa[i])[cc];
                    const float p2v = ((const float*)&pb[i])[cc];
#pragma unroll
                    for (int j = 0; j < 4; ++j) {
                        O1[i][j] += p1v * vv[j];
                        O2[i][j] += p2v * vv[j];
                    }
                }
            }
        }
    }

    // ---- epilogue: combine, per-row rmsnorm * (1-0.8), store ----
    const float lam = lamp[h];
#pragma unroll
    for (int i = 0; i < 4; ++i) {
        const float inv1 = 1.f / rl1[i];
        const float inv2 = 1.f / rl2[i];
        float o[4];
        float ss = 0.f;
#pragma unroll
        for (int j = 0; j < 4; ++j) {
            o[j] = O1[i][j]*inv1 - lam * (O2[i][j]*inv2);
            ss += o[j]*o[j];
        }
        ss = red_sum16(ss);
        const float scl = rsqrtf(ss * (1.0f/64.0f) + 1e-6f) * 0.2f;
        const int tq = qt*64 + ty*4 + i;
        float* ob = Og + ((size_t)(b*Sq + tq) * Hh + h) * 64;
#pragma unroll
        for (int j = 0; j < 4; ++j) ob[j*16 + tx] = o[j]*scl;
    }
}

// ---------------- silu(a) * b ----------------
__global__ void silu_mul_kernel(const float4* __restrict__ a, const float4* __restrict__ b,
                                float4* __restrict__ o)
{
    const int i = blockIdx.x * blockDim.x + threadIdx.x;
    float4 av = a[i], bv = b[i], r;
    r.x = av.x / (1.f + __expf(-av.x)) * bv.x;
    r.y = av.y / (1.f + __expf(-av.y)) * bv.y;
    r.z = av.z / (1.f + __expf(-av.z)) * bv.z;
    r.w = av.w / (1.f + __expf(-av.w)) * bv.w;
    o[i] = r;
}

// ---------------- launch ----------------
static void gemm(const float* A, const float* B, const float* R, float* C,
                 int M, int N, int K, int mode)
{
    dim3 grid(N / 128, M / 128);
    sgemm_kernel<<<grid, 256>>>(A, B, R, C, M, N, K, mode);
}

extern "C" void kernel_launch(void* const* d_in, const int* in_sizes, int n_in,
                              void* d_out, int out_size)
{
    const float* x    = (const float*)d_in[0];
    const float* enc  = (const float*)d_in[1];
    const float* Wq_s = (const float*)d_in[2];
    const float* Wk_s = (const float*)d_in[3];
    const float* Wv_s = (const float*)d_in[4];
    const float* Wo_s = (const float*)d_in[5];
    const float* lq1s = (const float*)d_in[6];
    const float* lk1s = (const float*)d_in[7];
    const float* lq2s = (const float*)d_in[8];
    const float* lk2s = (const float*)d_in[9];
    const float* Wq_c = (const float*)d_in[10];
    const float* Wk_c = (const float*)d_in[11];
    const float* Wv_c = (const float*)d_in[12];
    const float* Wo_c = (const float*)d_in[13];
    const float* lq1c = (const float*)d_in[14];
    const float* lk1c = (const float*)d_in[15];
    const float* lq2c = (const float*)d_in[16];
    const float* lk2c = (const float*)d_in[17];
    const float* grms = (const float*)d_in[18];
    const float* W1   = (const float*)d_in[19];
    const float* W2   = (const float*)d_in[20];
    const float* W3   = (const float*)d_in[21];
    float* out = (float*)d_out;

    float *hn, *q, *k, *v, *ao, *h1, *h2, *hn2, *m1, *m2, *lam;
    cudaGetSymbolAddress((void**)&hn,  g_hn);
    cudaGetSymbolAddress((void**)&q,   g_q);
    cudaGetSymbolAddress((void**)&k,   g_k);
    cudaGetSymbolAddress((void**)&v,   g_v);
    cudaGetSymbolAddress((void**)&ao,  g_ao);
    cudaGetSymbolAddress((void**)&h1,  g_h1);
    cudaGetSymbolAddress((void**)&h2,  g_h2);
    cudaGetSymbolAddress((void**)&hn2, g_hn2);
    cudaGetSymbolAddress((void**)&m1,  g_m1);
    cudaGetSymbolAddress((void**)&m2,  g_m2);
    cudaGetSymbolAddress((void**)&lam, g_lam);

    cudaFuncSetAttribute(flash_diff_kernel,
                         cudaFuncAttributeMaxDynamicSharedMemorySize, FL_SMEM);

    // h = rmsnorm(x, g)
    rmsnorm_kernel<<<ROWS, 256>>>(x, grms, hn);

    // ---- self diff-attention (causal) ----
    gemm(hn, Wq_s, nullptr, q, ROWS, 2048, 1024, 0);
    gemm(hn, Wk_s, nullptr, k, ROWS, 2048, 1024, 0);
    gemm(hn, Wv_s, nullptr, v, ROWS, 1024, 1024, 0);
    lambda_kernel<<<Hh, 32>>>(lq1s, lk1s, lq2s, lk2s, lam);
    flash_diff_kernel<<<dim3(Tt/64, Hh, Bb), 256, FL_SMEM>>>(q, k, v, lam, ao, Tt, Tt, 1);
    // h1 = ao @ Wo_s + hn
    gemm(ao, Wo_s, hn, h1, ROWS, 1024, 1024, 1);

    // ---- cross diff-attention (not causal), kv from encoder_output ----
    gemm(h1,  Wq_c, nullptr, q, ROWS, 2048, 1024, 0);
    gemm(enc, Wk_c, nullptr, k, ROWS, 2048, 1024, 0);
    gemm(enc, Wv_c, nullptr, v, ROWS, 1024, 1024, 0);
    lambda_kernel<<<Hh, 32>>>(lq1c, lk1c, lq2c, lk2c, lam + 16);
    flash_diff_kernel<<<dim3(Tt/64, Hh, Bb), 256, FL_SMEM>>>(q, k, v, lam + 16, ao, Tt, Tt, 0);
    // h2 = 2 * (ao @ Wo_c)   (h = attn; h = h + h)
    gemm(ao, Wo_c, nullptr, h2, ROWS, 1024, 1024, 2);

    // ---- MLP: out = swiglu(rmsnorm(h2)) + h2 ----
    rmsnorm_kernel<<<ROWS, 256>>>(h2, grms, hn2);
    gemm(hn2, W1, nullptr, m1, ROWS, DFF, 1024, 0);
    gemm(hn2, W2, nullptr, m2, ROWS, DFF, 1024, 0);
    silu_mul_kernel<<<(ROWS*DFF/4)/256, 256>>>((const float4*)m1, (const float4*)m2, (float4*)m1);
    gemm(m1, W3, h2, out, ROWS, 1024, DFF, 1);
}

// round 5
// speedup vs baseline: 1.6795x; 1.6795x over previous
#include <cuda_runtime.h>
#include <cuda_bf16.h>
#include <math.h>
#include <stdint.h>

// ---------------- problem dims (fixed) ----------------
#define Bb   4
#define Tt   1024
#define Dd   1024
#define Hh   16
#define HSs  64
#define DFF  4096
#define ROWS (Bb*Tt)      // 4096

// ---------------- scratch (device globals; no allocs allowed) ----------------
__device__ float g_hn [ROWS*Dd];
__device__ float g_q  [ROWS*2048];
__device__ float g_k  [ROWS*2048];
__device__ float g_v  [ROWS*1024];
__device__ float g_ao [ROWS*1024];
__device__ float g_h1 [ROWS*Dd];
__device__ float g_h2 [ROWS*Dd];
__device__ float g_hn2[ROWS*Dd];
__device__ float g_m1 [ROWS*DFF];
__device__ float g_m2 [ROWS*DFF];
__device__ float g_lam[32];

// bf16 hi/lo split buffers
#define NW_TOT (24u*1024u*1024u)            // all weights transposed, elements
__device__ __nv_bfloat16 g_whi[NW_TOT];
__device__ __nv_bfloat16 g_wlo[NW_TOT];
#define NA_TOT (ROWS*DFF)                   // largest activation (m1)
__device__ __nv_bfloat16 g_ahi[NA_TOT];
__device__ __nv_bfloat16 g_alo[NA_TOT];

// weight offsets (elements)
#define OW_QS (0u)
#define OW_KS (2u*1024u*1024u)
#define OW_VS (4u*1024u*1024u)
#define OW_OS (5u*1024u*1024u)
#define OW_QC (6u*1024u*1024u)
#define OW_KC (8u*1024u*1024u)
#define OW_VC (10u*1024u*1024u)
#define OW_OC (11u*1024u*1024u)
#define OW_W1 (12u*1024u*1024u)
#define OW_W2 (16u*1024u*1024u)
#define OW_W3 (20u*1024u*1024u)

// ================= small helpers =================
__device__ __forceinline__ uint32_t smem_u32(const void* p) {
    uint32_t a;
    asm("{ .reg .u64 t; cvta.to.shared.u64 t, %1; cvt.u32.u64 %0, t; }" : "=r"(a) : "l"(p));
    return a;
}
__device__ __forceinline__ void cp16(uint32_t dst, const void* src) {
    asm volatile("cp.async.cg.shared.global [%0], [%1], 16;" :: "r"(dst), "l"(src) : "memory");
}
__device__ __forceinline__ void cp_commit() {
    asm volatile("cp.async.commit_group;" ::: "memory");
}
__device__ __forceinline__ void cp_wait2() {
    asm volatile("cp.async.wait_group 2;" ::: "memory");
}

__device__ __forceinline__ void mma16816(float* d, const uint32_t* a, const uint32_t* b) {
    asm volatile(
        "mma.sync.aligned.m16n8k16.row.col.f32.bf16.bf16.f32 "
        "{%0,%1,%2,%3}, {%4,%5,%6,%7}, {%8,%9}, {%0,%1,%2,%3};"
        : "+f"(d[0]), "+f"(d[1]), "+f"(d[2]), "+f"(d[3])
        : "r"(a[0]), "r"(a[1]), "r"(a[2]), "r"(a[3]), "r"(b[0]), "r"(b[1]));
}

// ============ activation split: fp32 -> bf16 hi + bf16 lo ============
__global__ __launch_bounds__(256) void split_kernel(
    const float4* __restrict__ in, __nv_bfloat162* __restrict__ hi,
    __nv_bfloat162* __restrict__ lo, int n4)
{
    const int i = blockIdx.x * blockDim.x + threadIdx.x;
    if (i >= n4) return;
    float4 v = in[i];
    __nv_bfloat162 h01 = __floats2bfloat162_rn(v.x, v.y);
    __nv_bfloat162 h23 = __floats2bfloat162_rn(v.z, v.w);
    float2 f01 = __bfloat1622float2(h01);
    float2 f23 = __bfloat1622float2(h23);
    __nv_bfloat162 l01 = __floats2bfloat162_rn(v.x - f01.x, v.y - f01.y);
    __nv_bfloat162 l23 = __floats2bfloat162_rn(v.z - f23.x, v.w - f23.y);
    hi[2*i] = h01; hi[2*i+1] = h23;
    lo[2*i] = l01; lo[2*i+1] = l23;
}

// ============ weight split + transpose: B[K][N] fp32 -> Bt[N][K] bf16 hi/lo ============
__global__ __launch_bounds__(256) void split_t_kernel(
    const float* __restrict__ B, __nv_bfloat16* __restrict__ thi,
    __nv_bfloat16* __restrict__ tlo, int K, int N)
{
    __shared__ float tile[32][33];
    const int tx = threadIdx.x, ty = threadIdx.y;
    const int n0 = blockIdx.x * 32, k0 = blockIdx.y * 32;
#pragma unroll
    for (int j = ty; j < 32; j += 8)
        tile[j][tx] = B[(size_t)(k0 + j) * N + n0 + tx];
    __syncthreads();
#pragma unroll
    for (int j = ty; j < 32; j += 8) {
        float x = tile[tx][j];                  // B[k0+tx][n0+j]
        __nv_bfloat16 h = __float2bfloat16(x);
        __nv_bfloat16 l = __float2bfloat16(x - __bfloat162float(h));
        const size_t o = (size_t)(n0 + j) * K + k0 + tx;
        thi[o] = h; tlo[o] = l;
    }
}

// ============ bf16x3 tensor-core GEMM: C[M,N] = A[M,K] @ B[K,N] ============
// A given pre-split [M][K] hi/lo; B given pre-split-transposed [N][K] hi/lo.
// mode 0: store; 1: += R; 2: *2
#define BG_ROWB   80                          // padded smem row bytes (32 bf16 = 64B + 16B pad)
#define BG_BUF    (128*BG_ROWB)               // 10240 B per matrix buffer
#define BG_STAGE  (4*BG_BUF)                  // 40960 B
#define BG_SMEM   (3*BG_STAGE)                // 122880 B

__global__ __launch_bounds__(256) void bgemm_kernel(
    const __nv_bfloat16* __restrict__ Ahi, const __nv_bfloat16* __restrict__ Alo,
    const __nv_bfloat16* __restrict__ Bhi, const __nv_bfloat16* __restrict__ Blo,
    const float* __restrict__ R, float* __restrict__ C,
    int M, int N, int K, int mode)
{
    extern __shared__ char sm_c[];
    const uint32_t smb = smem_u32(sm_c);

    const int tid = threadIdx.x;
    const int wid = tid >> 5;
    const int lane = tid & 31;
    const int bm = blockIdx.y * 128, bn = blockIdx.x * 128;
    const int m0 = (wid >> 2) * 64;            // warp m offset in tile
    const int n0 = (wid & 3) * 32;             // warp n offset in tile
    const int qrow = lane >> 2;                // 0..7
    const int qk4 = (lane & 3) * 4;            // byte offset for k pair

    const int nch = K >> 5;                    // k-chunks of 32

    auto issue_stage = [&](int t) {
        const int k0 = t * 32;
        const uint32_t sb = smb + (uint32_t)(t % 3) * BG_STAGE;
#pragma unroll
        for (int c = 0; c < 2; ++c) {
            const int idx = tid + c * 256;     // 0..511
            const int row = idx >> 2, q = idx & 3;
            const uint32_t so = (uint32_t)row * BG_ROWB + q * 16;
            const size_t goA = (size_t)(bm + row) * K + k0 + q * 8;
            const size_t goB = (size_t)(bn + row) * K + k0 + q * 8;
            cp16(sb + so,            Ahi + goA);
            cp16(sb + BG_BUF + so,   Alo + goA);
            cp16(sb + 2*BG_BUF + so, Bhi + goB);
            cp16(sb + 3*BG_BUF + so, Blo + goB);
        }
        cp_commit();
    };

    issue_stage(0); issue_stage(1); issue_stage(2);

    float acc[4][4][4];
#pragma unroll
    for (int a = 0; a < 4; ++a)
#pragma unroll
        for (int b = 0; b < 4; ++b)
#pragma unroll
            for (int c = 0; c < 4; ++c) acc[a][b][c] = 0.f;

    for (int t = 0; t < nch; ++t) {
        cp_wait2();
        __syncthreads();
        const char* Ah = sm_c + (t % 3) * BG_STAGE;
        const char* Al = Ah + BG_BUF;
        const char* Bh = Ah + 2*BG_BUF;
        const char* Bl = Ah + 3*BG_BUF;
#pragma unroll
        for (int kb = 0; kb <= 32; kb += 32) {        // two k16 steps (byte offsets)
            uint32_t ahi[4][4], alo[4][4], bhi[4][2], blo[4][2];
#pragma unroll
            for (int mt = 0; mt < 4; ++mt) {
                const uint32_t off = (uint32_t)(m0 + mt*16 + qrow) * BG_ROWB + kb + qk4;
                ahi[mt][0] = *(const uint32_t*)(Ah + off);
                ahi[mt][1] = *(const uint32_t*)(Ah + off + 8*BG_ROWB);
                ahi[mt][2] = *(const uint32_t*)(Ah + off + 16);
                ahi[mt][3] = *(const uint32_t*)(Ah + off + 8*BG_ROWB + 16);
                alo[mt][0] = *(const uint32_t*)(Al + off);
                alo[mt][1] = *(const uint32_t*)(Al + off + 8*BG_ROWB);
                alo[mt][2] = *(const uint32_t*)(Al + off + 16);
                alo[mt][3] = *(const uint32_t*)(Al + off + 8*BG_ROWB + 16);
            }
#pragma unroll
            for (int nt = 0; nt < 4; ++nt) {
                const uint32_t off = (uint32_t)(n0 + nt*8 + qrow) * BG_ROWB + kb + qk4;
                bhi[nt][0] = *(const uint32_t*)(Bh + off);
                bhi[nt][1] = *(const uint32_t*)(Bh + off + 16);
                blo[nt][0] = *(const uint32_t*)(Bl + off);
                blo[nt][1] = *(const uint32_t*)(Bl + off + 16);
            }
#pragma unroll
            for (int mt = 0; mt < 4; ++mt)
#pragma unroll
                for (int nt = 0; nt < 4; ++nt) {
                    mma16816(acc[mt][nt], ahi[mt], bhi[nt]);
                    mma16816(acc[mt][nt], ahi[mt], blo[nt]);
                    mma16816(acc[mt][nt], alo[mt], bhi[nt]);
                }
        }
        __syncthreads();
        if (t + 3 < nch) issue_stage(t + 3);
        else cp_commit();                       // keep group accounting invariant
    }

    // ---- epilogue ----
#pragma unroll
    for (int mt = 0; mt < 4; ++mt) {
        const int r0 = bm + m0 + mt*16 + qrow;
#pragma unroll
        for (int nt = 0; nt < 4; ++nt) {
            const int c = bn + n0 + nt*8 + (lane & 3) * 2;
            float2 v0 = make_float2(acc[mt][nt][0], acc[mt][nt][1]);
            float2 v1 = make_float2(acc[mt][nt][2], acc[mt][nt][3]);
            if (mode == 1) {
                const float* q0 = R + (size_t)r0 * N + c;
                const float* q1 = R + (size_t)(r0 + 8) * N + c;
                v0.x += q0[0]; v0.y += q0[1];
                v1.x += q1[0]; v1.y += q1[1];
            } else if (mode == 2) {
                v0.x *= 2.f; v0.y *= 2.f; v1.x *= 2.f; v1.y *= 2.f;
            }
            *(float2*)(C + (size_t)r0 * N + c) = v0;
            *(float2*)(C + (size_t)(r0 + 8) * N + c) = v1;
        }
    }
}

// ---------------- helpers ----------------
__device__ __forceinline__ float red_max16(float v) {
#pragma unroll
    for (int o = 8; o; o >>= 1) v = fmaxf(v, __shfl_xor_sync(0xffffffffu, v, o));
    return v;
}
__device__ __forceinline__ float red_sum16(float v) {
#pragma unroll
    for (int o = 8; o; o >>= 1) v += __shfl_xor_sync(0xffffffffu, v, o);
    return v;
}

// ---------------- rmsnorm: one block per row of 1024 ----------------
__global__ __launch_bounds__(256) void rmsnorm_kernel(
    const float* __restrict__ x, const float* __restrict__ g, float* __restrict__ out)
{
    __shared__ float red[8];
    __shared__ float sscale;
    const int row = blockIdx.x;
    const int t = threadIdx.x;
    const float4* xr = (const float4*)(x + (size_t)row * 1024);
    float4 v = xr[t];
    float ss = v.x*v.x + v.y*v.y + v.z*v.z + v.w*v.w;
#pragma unroll
    for (int o = 16; o; o >>= 1) ss += __shfl_xor_sync(0xffffffffu, ss, o);
    if ((t & 31) == 0) red[t >> 5] = ss;
    __syncthreads();
    if (t == 0) {
        float s = 0.f;
#pragma unroll
        for (int i = 0; i < 8; ++i) s += red[i];
        sscale = rsqrtf(s * (1.0f/1024.0f) + 1e-6f);
    }
    __syncthreads();
    const float sc = sscale;
    float4 gv = ((const float4*)g)[t];
    float4 o;
    o.x = v.x*sc*gv.x; o.y = v.y*sc*gv.y; o.z = v.z*sc*gv.z; o.w = v.w*sc*gv.w;
    ((float4*)(out + (size_t)row * 1024))[t] = o;
}

// ---------------- lambda ----------------
__global__ void lambda_kernel(const float* __restrict__ lq1, const float* __restrict__ lk1,
                              const float* __restrict__ lq2, const float* __restrict__ lk2,
                              float* __restrict__ lam)
{
    const int h = blockIdx.x;
    const int lane = threadIdx.x;
    float s1 = 0.f, s2 = 0.f;
    for (int d = lane; d < 64; d += 32) {
        s1 += lq1[h*64 + d] * lk1[h*64 + d];
        s2 += lq2[h*64 + d] * lk2[h*64 + d];
    }
#pragma unroll
    for (int o = 16; o; o >>= 1) {
        s1 += __shfl_xor_sync(0xffffffffu, s1, o);
        s2 += __shfl_xor_sync(0xffffffffu, s2, o);
    }
    if (lane == 0) lam[h] = expf(s1) - expf(s2) + 0.8f;
}

// ---------------- flash diff-attention (unchanged, fp32) ----------------
#define FL_SMEM ((4*64*68 + 64*64) * 4)

__global__ __launch_bounds__(256) void flash_diff_kernel(
    const float* __restrict__ Q, const float* __restrict__ Kg,
    const float* __restrict__ Vg, const float* __restrict__ lamp,
    float* __restrict__ Og, int Sq, int Sk, int causal)
{
    extern __shared__ float sm[];
    float* Qs1 = sm;
    float* Qs2 = Qs1 + 64*68;
    float* KP1 = Qs2 + 64*68;
    float* KP2 = KP1 + 64*68;
    float* Vs  = KP2 + 64*68;

    const int tid = threadIdx.x;
    const int tx = tid & 15, ty = tid >> 4;
    const int qt = blockIdx.x, h = blockIdx.y, b = blockIdx.z;

    {
        const int r = tid >> 2;
        const int d0 = (tid & 3) << 4;
        const float* qb = Q + ((size_t)(b*Sq + qt*64 + r) * Hh + h) * 128 + d0;
#pragma unroll
        for (int u = 0; u < 16; u += 4) {
            *(float4*)&Qs1[r*68 + d0 + u] = *(const float4*)(qb + u);
            *(float4*)&Qs2[r*68 + d0 + u] = *(const float4*)(qb + 64 + u);
        }
    }

    float O1[4][4], O2[4][4];
    float rm1[4], rl1[4], rm2[4], rl2[4];
#pragma unroll
    for (int i = 0; i < 4; ++i) {
        rm1[i] = rm2[i] = -1e30f; rl1[i] = rl2[i] = 0.f;
#pragma unroll
        for (int j = 0; j < 4; ++j) { O1[i][j] = 0.f; O2[i][j] = 0.f; }
    }
    const float scale = 0.125f;
    const int nkt = causal ? (qt + 1) : (Sk >> 6);

    for (int kt = 0; kt < nkt; ++kt) {
        __syncthreads();
        {
            const int c = tid >> 2;
            const int d0 = (tid & 3) << 4;
            const float* kb = Kg + ((size_t)(b*Sk + kt*64 + c) * Hh + h) * 128 + d0;
            const float* vb = Vg + ((size_t)(b*Sk + kt*64 + c) * Hh + h) * 64 + d0;
#pragma unroll
            for (int u = 0; u < 16; u += 4) {
                *(float4*)&KP1[c*68 + d0 + u] = *(const float4*)(kb + u);
                *(float4*)&KP2[c*68 + d0 + u] = *(const float4*)(kb + 64 + u);
                *(float4*)&Vs [c*64 + d0 + u] = *(const float4*)(vb + u);
            }
        }
        __syncthreads();

        float s1[4][4], s2[4][4];
#pragma unroll
        for (int i = 0; i < 4; ++i)
#pragma unroll
            for (int j = 0; j < 4; ++j) { s1[i][j] = 0.f; s2[i][j] = 0.f; }

#pragma unroll 4
        for (int k4 = 0; k4 < 64; k4 += 4) {
            float4 qa[4], qb[4], ka[4], kb[4];
#pragma unroll
            for (int i = 0; i < 4; ++i) {
                qa[i] = *(const float4*)&Qs1[(ty*4+i)*68 + k4];
                qb[i] = *(const float4*)&Qs2[(ty*4+i)*68 + k4];
            }
#pragma unroll
            for (int j = 0; j < 4; ++j) {
                ka[j] = *(const float4*)&KP1[(j*16+tx)*68 + k4];
                kb[j] = *(const float4*)&KP2[(j*16+tx)*68 + k4];
            }
#pragma unroll
            for (int i = 0; i < 4; ++i)
#pragma unroll
                for (int j = 0; j < 4; ++j) {
                    s1[i][j] += qa[i].x*ka[j].x + qa[i].y*ka[j].y + qa[i].z*ka[j].z + qa[i].w*ka[j].w;
                    s2[i][j] += qb[i].x*kb[j].x + qb[i].y*kb[j].y + qb[i].z*kb[j].z + qb[i].w*kb[j].w;
                }
        }

        const bool maskdiag = (causal != 0) && (kt == qt);
        __syncthreads();

#pragma unroll
        for (int i = 0; i < 4; ++i) {
            const int r = ty*4 + i;
            float tm = -1e30f;
#pragma unroll
            for (int j = 0; j < 4; ++j) {
                s1[i][j] *= scale;
                if (maskdiag && (j*16 + tx) > r) s1[i][j] = -1e9f;
                tm = fmaxf(tm, s1[i][j]);
            }
            tm = red_max16(tm);
            float mn = fmaxf(rm1[i], tm);
            float al = __expf(rm1[i] - mn);
            rm1[i] = mn;
            float rs = 0.f;
#pragma unroll
            for (int j = 0; j < 4; ++j) {
                float p = __expf(s1[i][j] - mn);
                rs += p;
                KP1[r*68 + j*16 + tx] = p;
            }
            rs = red_sum16(rs);
            rl1[i] = rl1[i]*al + rs;
#pragma unroll
            for (int j = 0; j < 4; ++j) O1[i][j] *= al;

            float tm2 = -1e30f;
#pragma unroll
            for (int j = 0; j < 4; ++j) {
                s2[i][j] *= scale;
                if (maskdiag && (j*16 + tx) > r) s2[i][j] = -1e9f;
                tm2 = fmaxf(tm2, s2[i][j]);
            }
            tm2 = red_max16(tm2);
            float mn2 = fmaxf(rm2[i], tm2);
            float al2 = __expf(rm2[i] - mn2);
            rm2[i] = mn2;
            float rs2 = 0.f;
#pragma unroll
            for (int j = 0; j < 4; ++j) {
                float p = __expf(s2[i][j] - mn2);
                rs2 += p;
                KP2[r*68 + j*16 + tx] = p;
            }
            rs2 = red_sum16(rs2);
            rl2[i] = rl2[i]*al2 + rs2;
#pragma unroll
            for (int j = 0; j < 4; ++j) O2[i][j] *= al2;
        }
        __syncthreads();

#pragma unroll 4
        for (int c4 = 0; c4 < 64; c4 += 4) {
            float4 pa[4], pb[4];
#pragma unroll
            for (int i = 0; i < 4; ++i) {
                pa[i] = *(const float4*)&KP1[(ty*4+i)*68 + c4];
                pb[i] = *(const float4*)&KP2[(ty*4+i)*68 + c4];
            }
#pragma unroll
            for (int cc = 0; cc < 4; ++cc) {
                float vv[4];
#pragma unroll
                for (int j = 0; j < 4; ++j) vv[j] = Vs[(c4+cc)*64 + j*16 + tx];
#pragma unroll
                for (int i = 0; i < 4; ++i) {
                    const float p1v = ((const float*)&pa[i])[cc];
                    const float p2v = ((const float*)&pb[i])[cc];
#pragma unroll
                    for (int j = 0; j < 4; ++j) {
                        O1[i][j] += p1v * vv[j];
                        O2[i][j] += p2v * vv[j];
                    }
                }
            }
        }
    }

    const float lam = lamp[h];
#pragma unroll
    for (int i = 0; i < 4; ++i) {
        const float inv1 = 1.f / rl1[i];
        const float inv2 = 1.f / rl2[i];
        float o[4];
        float ss = 0.f;
#pragma unroll
        for (int j = 0; j < 4; ++j) {
            o[j] = O1[i][j]*inv1 - lam * (O2[i][j]*inv2);
            ss += o[j]*o[j];
        }
        ss = red_sum16(ss);
        const float scl = rsqrtf(ss * (1.0f/64.0f) + 1e-6f) * 0.2f;
        const int tq = qt*64 + ty*4 + i;
        float* ob = Og + ((size_t)(b*Sq + tq) * Hh + h) * 64;
#pragma unroll
        for (int j = 0; j < 4; ++j) ob[j*16 + tx] = o[j]*scl;
    }
}

// ---------------- silu(a) * b ----------------
__global__ void silu_mul_kernel(const float4* __restrict__ a, const float4* __restrict__ b,
                                float4* __restrict__ o)
{
    const int i = blockIdx.x * blockDim.x + threadIdx.x;
    float4 av = a[i], bv = b[i], r;
    r.x = av.x / (1.f + __expf(-av.x)) * bv.x;
    r.y = av.y / (1.f + __expf(-av.y)) * bv.y;
    r.z = av.z / (1.f + __expf(-av.z)) * bv.z;
    r.w = av.w / (1.f + __expf(-av.w)) * bv.w;
    o[i] = r;
}

// ---------------- host-side launch helpers ----------------
static __nv_bfloat16 *s_whi, *s_wlo, *s_ahi, *s_alo;

static void splitA(const float* src, int nelem) {
    const int n4 = nelem / 4;
    split_kernel<<<(n4 + 255) / 256, 256>>>(
        (const float4*)src, (__nv_bfloat162*)s_ahi, (__nv_bfloat162*)s_alo, n4);
}
static void splitW(const float* W, uint32_t off, int K, int N) {
    split_t_kernel<<<dim3(N/32, K/32), dim3(32, 8)>>>(W, s_whi + off, s_wlo + off, K, N);
}
static void gemm(uint32_t woff, const float* R, float* C, int M, int N, int K, int mode) {
    dim3 grid(N / 128, M / 128);
    bgemm_kernel<<<grid, 256, BG_SMEM>>>(s_ahi, s_alo, s_whi + woff, s_wlo + woff,
                                         R, C, M, N, K, mode);
}

extern "C" void kernel_launch(void* const* d_in, const int* in_sizes, int n_in,
                              void* d_out, int out_size)
{
    const float* x    = (const float*)d_in[0];
    const float* enc  = (const float*)d_in[1];
    const float* Wq_s = (const float*)d_in[2];
    const float* Wk_s = (const float*)d_in[3];
    const float* Wv_s = (const float*)d_in[4];
    const float* Wo_s = (const float*)d_in[5];
    const float* lq1s = (const float*)d_in[6];
    const float* lk1s = (const float*)d_in[7];
    const float* lq2s = (const float*)d_in[8];
    const float* lk2s = (const float*)d_in[9];
    const float* Wq_c = (const float*)d_in[10];
    const float* Wk_c = (const float*)d_in[11];
    const float* Wv_c = (const float*)d_in[12];
    const float* Wo_c = (const float*)d_in[13];
    const float* lq1c = (const float*)d_in[14];
    const float* lk1c = (const float*)d_in[15];
    const float* lq2c = (const float*)d_in[16];
    const float* lk2c = (const float*)d_in[17];
    const float* grms = (const float*)d_in[18];
    const float* W1   = (const float*)d_in[19];
    const float* W2   = (const float*)d_in[20];
    const float* W3   = (const float*)d_in[21];
    float* out = (float*)d_out;

    float *hn, *q, *k, *v, *ao, *h1, *h2, *hn2, *m1, *m2, *lam;
    cudaGetSymbolAddress((void**)&hn,  g_hn);
    cudaGetSymbolAddress((void**)&q,   g_q);
    cudaGetSymbolAddress((void**)&k,   g_k);
    cudaGetSymbolAddress((void**)&v,   g_v);
    cudaGetSymbolAddress((void**)&ao,  g_ao);
    cudaGetSymbolAddress((void**)&h1,  g_h1);
    cudaGetSymbolAddress((void**)&h2,  g_h2);
    cudaGetSymbolAddress((void**)&hn2, g_hn2);
    cudaGetSymbolAddress((void**)&m1,  g_m1);
    cudaGetSymbolAddress((void**)&m2,  g_m2);
    cudaGetSymbolAddress((void**)&lam, g_lam);
    cudaGetSymbolAddress((void**)&s_whi, g_whi);
    cudaGetSymbolAddress((void**)&s_wlo, g_wlo);
    cudaGetSymbolAddress((void**)&s_ahi, g_ahi);
    cudaGetSymbolAddress((void**)&s_alo, g_alo);

    cudaFuncSetAttribute(flash_diff_kernel,
                         cudaFuncAttributeMaxDynamicSharedMemorySize, FL_SMEM);
    cudaFuncSetAttribute(bgemm_kernel,
                         cudaFuncAttributeMaxDynamicSharedMemorySize, BG_SMEM);

    // ---- weight split+transpose (bf16 hi/lo, [N][K]) ----
    splitW(Wq_s, OW_QS, 1024, 2048);
    splitW(Wk_s, OW_KS, 1024, 2048);
    splitW(Wv_s, OW_VS, 1024, 1024);
    splitW(Wo_s, OW_OS, 1024, 1024);
    splitW(Wq_c, OW_QC, 1024, 2048);
    splitW(Wk_c, OW_KC, 1024, 2048);
    splitW(Wv_c, OW_VC, 1024, 1024);
    splitW(Wo_c, OW_OC, 1024, 1024);
    splitW(W1,   OW_W1, 1024, 4096);
    splitW(W2,   OW_W2, 1024, 4096);
    splitW(W3,   OW_W3, 4096, 1024);

    // h = rmsnorm(x, g)
    rmsnorm_kernel<<<ROWS, 256>>>(x, grms, hn);

    // ---- self diff-attention (causal) ----
    splitA(hn, ROWS*1024);
    gemm(OW_QS, nullptr, q, ROWS, 2048, 1024, 0);
    gemm(OW_KS, nullptr, k, ROWS, 2048, 1024, 0);
    gemm(OW_VS, nullptr, v, ROWS, 1024, 1024, 0);
    lambda_kernel<<<Hh, 32>>>(lq1s, lk1s, lq2s, lk2s, lam);
    flash_diff_kernel<<<dim3(Tt/64, Hh, Bb), 256, FL_SMEM>>>(q, k, v, lam, ao, Tt, Tt, 1);
    splitA(ao, ROWS*1024);
    gemm(OW_OS, hn, h1, ROWS, 1024, 1024, 1);

    // ---- cross diff-attention (not causal) ----
    splitA(h1, ROWS*1024);
    gemm(OW_QC, nullptr, q, ROWS, 2048, 1024, 0);
    splitA(enc, ROWS*1024);
    gemm(OW_KC, nullptr, k, ROWS, 2048, 1024, 0);
    gemm(OW_VC, nullptr, v, ROWS, 1024, 1024, 0);
    lambda_kernel<<<Hh, 32>>>(lq1c, lk1c, lq2c, lk2c, lam + 16);
    flash_diff_kernel<<<dim3(Tt/64, Hh, Bb), 256, FL_SMEM>>>(q, k, v, lam + 16, ao, Tt, Tt, 0);
    splitA(ao, ROWS*1024);
    gemm(OW_OC, nullptr, h2, ROWS, 1024, 1024, 2);

    // ---- MLP ----
    rmsnorm_kernel<<<ROWS, 256>>>(h2, grms, hn2);
    splitA(hn2, ROWS*1024);
    gemm(OW_W1, nullptr, m1, ROWS, DFF, 1024, 0);
    gemm(OW_W2, nullptr, m2, ROWS, DFF, 1024, 0);
    silu_mul_kernel<<<(ROWS*DFF/4)/256, 256>>>((const float4*)m1, (const float4*)m2, (float4*)m1);
    splitA(m1, ROWS*DFF);
    gemm(OW_W3, h2, out, ROWS, 1024, DFF, 1);
}